// round 7
// baseline (speedup 1.0000x reference)
#include <cuda_runtime.h>
#include <cuda_bf16.h>
#include <math.h>
#include <stdint.h>

#define NB 32
#define SS 512
#define DM 256
#define NH 8
#define HDIM 64
#define NLAYER 5
#define FFD 1024
#define OUTD 4096
#define NT (NB*SS)     /* 16384 tokens */
#define QKV 512        /* H*HD */

// ---------------- scratch (no allocations allowed) ----------------
__device__ float g_h [NT*DM];
__device__ float g_p [NT*DM];
__device__ float g_pe[SS*DM];
__device__ float g_bqkv[NLAYER*1536];
__device__ __nv_bfloat16 g_hh [NT*DM];
__device__ __nv_bfloat16 g_hl [NT*DM];
__device__ __nv_bfloat16 g_qkvh[NT*1536];
__device__ __nv_bfloat16 g_qkvl[NT*1536];
__device__ __nv_bfloat16 g_ohi[NT*QKV];
__device__ __nv_bfloat16 g_olo[NT*QKV];
__device__ __nv_bfloat16 g_ffh[NT*FFD];
__device__ __nv_bfloat16 g_ffl[NT*FFD];
#define WT_TOTAL 6291456
__device__ __nv_bfloat16 g_wth[WT_TOTAL];
__device__ __nv_bfloat16 g_wtl[WT_TOTAL];

// weight-transpose offsets (elements); wq/wk/wv contiguous per layer -> fused QKV B
#define WQT(i) ((size_t)(i)*1048576)
#define WOT(i) (WQT(i)+393216)
#define W1T(i) (WQT(i)+524288)
#define W2T(i) (WQT(i)+786432)
#define OWT    ((size_t)5242880)

// ---------------- helpers ----------------
__device__ __forceinline__ uint32_t smem_u32(const void* p) {
    uint32_t a;
    asm("{ .reg .u64 t; cvta.to.shared.u64 t, %1; cvt.u32.u64 %0, t; }" : "=r"(a) : "l"(p));
    return a;
}
__device__ __forceinline__ void split_bf16(float v, __nv_bfloat16& hi, __nv_bfloat16& lo) {
    hi = __float2bfloat16(v);
    lo = __float2bfloat16(v - __bfloat162float(hi));
}
__device__ __forceinline__ void split2(float a, float b, uint32_t& hi, uint32_t& lo) {
    __nv_bfloat16 ha = __float2bfloat16(a), hb = __float2bfloat16(b);
    __nv_bfloat16 la = __float2bfloat16(a - __bfloat162float(ha));
    __nv_bfloat16 lb = __float2bfloat16(b - __bfloat162float(hb));
    __nv_bfloat162 ph; ph.x = ha; ph.y = hb;
    __nv_bfloat162 pl; pl.x = la; pl.y = lb;
    hi = *(uint32_t*)&ph; lo = *(uint32_t*)&pl;
}
__device__ __forceinline__ void cp16(uint32_t dst, const void* src) {
    asm volatile("cp.async.cg.shared.global [%0], [%1], 16;" :: "r"(dst), "l"(src));
}
__device__ __forceinline__ void ldmx4(uint32_t* r, uint32_t addr) {
    asm volatile("ldmatrix.sync.aligned.m8n8.x4.shared.b16 {%0,%1,%2,%3}, [%4];"
        : "=r"(r[0]), "=r"(r[1]), "=r"(r[2]), "=r"(r[3]) : "r"(addr));
}
__device__ __forceinline__ void ldmx4t(uint32_t* r, uint32_t addr) {
    asm volatile("ldmatrix.sync.aligned.m8n8.x4.trans.shared.b16 {%0,%1,%2,%3}, [%4];"
        : "=r"(r[0]), "=r"(r[1]), "=r"(r[2]), "=r"(r[3]) : "r"(addr));
}
__device__ __forceinline__ void mma16816(float* d, const uint32_t* a, const uint32_t* b) {
    asm volatile("mma.sync.aligned.m16n8k16.row.col.f32.bf16.bf16.f32 "
        "{%0,%1,%2,%3}, {%4,%5,%6,%7}, {%8,%9}, {%0,%1,%2,%3};"
        : "+f"(d[0]), "+f"(d[1]), "+f"(d[2]), "+f"(d[3])
        : "r"(a[0]), "r"(a[1]), "r"(a[2]), "r"(a[3]), "r"(b[0]), "r"(b[1]));
}

// ---------------- positional encoding ----------------
__global__ void pe_kernel(float* __restrict__ pe) {
    int s = blockIdx.x, d = threadIdx.x;
    int i = d >> 1;
    float div = powf(10000.0f, (float)(2*i) / (float)DM);
    float ang = (float)s / div;
    pe[s*DM + d] = (d & 1) ? cosf(ang) : sinf(ang);
}

// ---------------- embedding + PE (+ bf16 split) ----------------
__global__ void embed_kernel(const int* __restrict__ x, const float* __restrict__ emb,
                             const float* __restrict__ pe, float* __restrict__ h,
                             __nv_bfloat16* __restrict__ hh, __nv_bfloat16* __restrict__ hl) {
    int t = blockIdx.x, d = threadIdx.x;
    int tok = x[t];
    int s = t & (SS-1);
    float v = emb[tok*DM + d] + pe[s*DM + d];
    h[(size_t)t*DM + d] = v;
    __nv_bfloat16 hi, lo; split_bf16(v, hi, lo);
    hh[(size_t)t*DM + d] = hi;
    hl[(size_t)t*DM + d] = lo;
}

// ---------------- pack QKV biases: [NL][1536] ----------------
__global__ void pack_bias(const float* __restrict__ bq, const float* __restrict__ bk,
                          const float* __restrict__ bv, float* __restrict__ out) {
    int i = blockIdx.x, d = threadIdx.x;
    out[i*1536 + d]        = bq[i*QKV + d];
    out[i*1536 + 512 + d]  = bk[i*QKV + d];
    out[i*1536 + 1024 + d] = bv[i*QKV + d];
}

// ---------------- weight transpose + split (layer-batched) ----------------
__global__ void wsplit(const float* __restrict__ W, __nv_bfloat16* __restrict__ Thi,
                       __nv_bfloat16* __restrict__ Tlo, int K, int N,
                       size_t lsrc, size_t ldst) {
    __shared__ float t[32][33];
    const float* Ws = W + (size_t)blockIdx.z * lsrc;
    __nv_bfloat16* Th = Thi + (size_t)blockIdx.z * ldst;
    __nv_bfloat16* Tl = Tlo + (size_t)blockIdx.z * ldst;
    int k0 = blockIdx.x*32, n0 = blockIdx.y*32;
    int tx = threadIdx.x, ty = threadIdx.y;  // 32 x 8
    #pragma unroll
    for (int i = 0; i < 32; i += 8)
        t[ty+i][tx] = Ws[(size_t)(k0+ty+i)*N + n0+tx];
    __syncthreads();
    #pragma unroll
    for (int i = 0; i < 32; i += 8) {
        float v = t[tx][ty+i];
        __nv_bfloat16 hi, lo; split_bf16(v, hi, lo);
        Th[(size_t)(n0+ty+i)*K + k0+tx] = hi;
        Tl[(size_t)(n0+ty+i)*K + k0+tx] = lo;
    }
}

// ---------------- HMMA bf16x3 GEMM ----------------
#define GBM 128
#define GBN 128
#define GBK 32
#define ROWB 80
#define TILEB (128*ROWB)
#define OFF_AHI 0
#define OFF_ALO TILEB
#define OFF_BHI (2*TILEB)
#define OFF_BLO (3*TILEB)
#define STAGEB (4*TILEB)
#define GSMEM (2*STAGEB)

__global__ void __launch_bounds__(256, 1)
gemm_mma(const __nv_bfloat16* __restrict__ Ahi, const __nv_bfloat16* __restrict__ Alo,
         const __nv_bfloat16* __restrict__ Bhi, const __nv_bfloat16* __restrict__ Blo,
         const float* __restrict__ bias,
         float* __restrict__ Cf, __nv_bfloat16* __restrict__ Chi, __nv_bfloat16* __restrict__ Clo,
         int Ncols, int K, int mode, int relu) {
    extern __shared__ char smem[];
    uint32_t sb = smem_u32(smem);
    int tid = threadIdx.x;
    int lane = tid & 31;
    int wid = tid >> 5;
    int warp_m = wid & 1;
    int warp_n = wid >> 1;
    int row0 = blockIdx.y * GBM;
    int col0 = blockIdx.x * GBN;

    int lr  = tid >> 2;
    int lc  = tid & 3;
    uint32_t sm_off0 = (uint32_t)(lr * ROWB + lc * 16);
    uint32_t sm_off1 = (uint32_t)((lr + 64) * ROWB + lc * 16);

#define LOAD_STAGE(bufidx, chunk) do { \
    uint32_t so = sb + (uint32_t)(bufidx)*STAGEB; \
    int kc = (chunk)*GBK + lc*8; \
    size_t ga0 = (size_t)(row0 + lr)      * K + kc; \
    size_t ga1 = (size_t)(row0 + lr + 64) * K + kc; \
    size_t gb0 = (size_t)(col0 + lr)      * K + kc; \
    size_t gb1 = (size_t)(col0 + lr + 64) * K + kc; \
    cp16(so + OFF_AHI + sm_off0, Ahi + ga0); \
    cp16(so + OFF_AHI + sm_off1, Ahi + ga1); \
    cp16(so + OFF_ALO + sm_off0, Alo + ga0); \
    cp16(so + OFF_ALO + sm_off1, Alo + ga1); \
    cp16(so + OFF_BHI + sm_off0, Bhi + gb0); \
    cp16(so + OFF_BHI + sm_off1, Bhi + gb1); \
    cp16(so + OFF_BLO + sm_off0, Blo + gb0); \
    cp16(so + OFF_BLO + sm_off1, Blo + gb1); \
} while(0)

    uint32_t a_row = (uint32_t)(warp_m*64 + (lane & 15));
    uint32_t a_off = a_row * ROWB + ((uint32_t)(lane >> 4)) * 16;
    uint32_t b_row = (uint32_t)(warp_n*32 + (lane & 7) + ((lane >> 4) << 3));
    uint32_t b_off = b_row * ROWB + ((uint32_t)((lane >> 3) & 1)) * 16;

    float acc[4][4][4];
    #pragma unroll
    for (int i = 0; i < 4; i++)
        #pragma unroll
        for (int j = 0; j < 4; j++)
            #pragma unroll
            for (int e = 0; e < 4; e++) acc[i][j][e] = 0.0f;

    int nch = K / GBK;
    LOAD_STAGE(0, 0);
    asm volatile("cp.async.commit_group;" ::: "memory");

    for (int c = 0; c < nch; c++) {
        int buf = c & 1;
        asm volatile("cp.async.wait_group 0;" ::: "memory");
        __syncthreads();
        if (c + 1 < nch) {
            LOAD_STAGE((c + 1) & 1, c + 1);
            asm volatile("cp.async.commit_group;" ::: "memory");
        }

        uint32_t so = sb + (uint32_t)buf * STAGEB;
        #pragma unroll
        for (int s = 0; s < 2; s++) {
            uint32_t ks = (uint32_t)(s * 32);
            uint32_t ah[4][4], al[4][4];
            #pragma unroll
            for (int mi = 0; mi < 4; mi++) {
                uint32_t ao = a_off + (uint32_t)(mi*16) * ROWB + ks;
                ldmx4(ah[mi], so + OFF_AHI + ao);
                ldmx4(al[mi], so + OFF_ALO + ao);
            }
            uint32_t bh[2][4], bl[2][4];
            #pragma unroll
            for (int nt = 0; nt < 2; nt++) {
                uint32_t bo = b_off + (uint32_t)(nt*16) * ROWB + ks;
                ldmx4(bh[nt], so + OFF_BHI + bo);
                ldmx4(bl[nt], so + OFF_BLO + bo);
            }
            #pragma unroll
            for (int mi = 0; mi < 4; mi++)
                #pragma unroll
                for (int nj = 0; nj < 4; nj++) {
                    const uint32_t* ph = &bh[nj >> 1][(nj & 1) * 2];
                    const uint32_t* pl = &bl[nj >> 1][(nj & 1) * 2];
                    mma16816(acc[mi][nj], ah[mi], ph);
                    mma16816(acc[mi][nj], ah[mi], pl);
                    mma16816(acc[mi][nj], al[mi], ph);
                }
        }
        __syncthreads();
    }

    int em = row0 + warp_m*64 + (lane >> 2);
    int en = col0 + warp_n*32 + (lane & 3) * 2;
    #pragma unroll
    for (int mi = 0; mi < 4; mi++) {
        #pragma unroll
        for (int nj = 0; nj < 4; nj++) {
            int cc = en + nj*8;
            float b0 = bias[cc], b1 = bias[cc + 1];
            #pragma unroll
            for (int half = 0; half < 2; half++) {
                int rr = em + mi*16 + half*8;
                float v0 = acc[mi][nj][half*2 + 0] + b0;
                float v1 = acc[mi][nj][half*2 + 1] + b1;
                if (relu) { v0 = fmaxf(v0, 0.0f); v1 = fmaxf(v1, 0.0f); }
                size_t idx = (size_t)rr * Ncols + cc;
                if (mode == 0) {
                    *(float2*)(Cf + idx) = make_float2(v0, v1);
                } else {
                    uint32_t hi, lo;
                    split2(v0, v1, hi, lo);
                    *(uint32_t*)(Chi + idx) = hi;
                    *(uint32_t*)(Clo + idx) = lo;
                }
            }
        }
    }
#undef LOAD_STAGE
}

// ---------------- HMMA flash attention (bf16x3 split) ----------------
// grid (8 qtiles, 256 bh), 128 threads (4 warps x m16). QKV packed [t][1536] hi/lo.
#define ATS 144                /* bytes per 64-bf16 row (128 data + 16 pad) */
#define ATILE (64*ATS)         /* 9216 */
#define ASMEM (6*ATILE)        /* 55296 */

__global__ void __launch_bounds__(128, 3)
attn_mma(const __nv_bfloat16* __restrict__ Xh, const __nv_bfloat16* __restrict__ Xl,
         __nv_bfloat16* __restrict__ Ohi, __nv_bfloat16* __restrict__ Olo) {
    extern __shared__ char smem[];
    uint32_t sb = smem_u32(smem);
    uint32_t sQh = sb,          sQl = sb +   ATILE;
    uint32_t sKh = sb + 2*ATILE, sKl = sb + 3*ATILE;
    uint32_t sVh = sb + 4*ATILE, sVl = sb + 5*ATILE;

    int tid = threadIdx.x, lane = tid & 31, w = tid >> 5;
    int qt = blockIdx.x, bh = blockIdx.y;
    int b = bh >> 3, h = bh & 7;
    int q0 = qt * 64;
    size_t gq = ((size_t)b * SS) * 1536 + h * HDIM;

    // load Q tile (hi/lo)
    {
        int r = tid >> 1, cg = (tid & 1) * 4;
        size_t go = gq + (size_t)(q0 + r) * 1536 + cg * 8;
        uint32_t so = (uint32_t)(r * ATS + cg * 16);
        #pragma unroll
        for (int c = 0; c < 4; c++) {
            cp16(sQh + so + c*16, Xh + go + c*8);
            cp16(sQl + so + c*16, Xl + go + c*8);
        }
    }
    asm volatile("cp.async.commit_group;" ::: "memory");
    asm volatile("cp.async.wait_group 0;" ::: "memory");
    __syncthreads();

    uint32_t qh[4][4], ql[4][4];
    #pragma unroll
    for (int ks = 0; ks < 4; ks++) {
        uint32_t ao = (uint32_t)((w*16 + (lane & 15)) * ATS + (lane >> 4)*16 + ks*32);
        ldmx4(qh[ks], sQh + ao);
        ldmx4(ql[ks], sQl + ao);
    }

    float mrow0 = -1e30f, mrow1 = -1e30f, lrow0 = 0.0f, lrow1 = 0.0f;
    float o[8][4];
    #pragma unroll
    for (int dt = 0; dt < 8; dt++)
        #pragma unroll
        for (int e = 0; e < 4; e++) o[dt][e] = 0.0f;

    for (int kt = 0; kt <= qt; kt++) {
        // load K/V tiles (hi/lo)
        {
            int r = tid >> 1, cg = (tid & 1) * 4;
            size_t go = gq + (size_t)(kt*64 + r) * 1536 + cg * 8;
            uint32_t so = (uint32_t)(r * ATS + cg * 16);
            #pragma unroll
            for (int c = 0; c < 4; c++) {
                cp16(sKh + so + c*16, Xh + go + 512  + c*8);
                cp16(sKl + so + c*16, Xl + go + 512  + c*8);
                cp16(sVh + so + c*16, Xh + go + 1024 + c*8);
                cp16(sVl + so + c*16, Xl + go + 1024 + c*8);
            }
        }
        asm volatile("cp.async.commit_group;" ::: "memory");
        asm volatile("cp.async.wait_group 0;" ::: "memory");
        __syncthreads();

        // scores S = Q K^T (bf16x3)
        float s[8][4];
        #pragma unroll
        for (int nt = 0; nt < 8; nt++)
            #pragma unroll
            for (int e = 0; e < 4; e++) s[nt][e] = 0.0f;

        #pragma unroll
        for (int p = 0; p < 4; p++) {
            #pragma unroll
            for (int ks = 0; ks < 4; ks++) {
                uint32_t kfh[4], kfl[4];
                uint32_t bo = (uint32_t)((p*16 + (lane & 7) + ((lane >> 4) << 3)) * ATS
                                         + ((lane >> 3) & 1)*16 + ks*32);
                ldmx4(kfh, sKh + bo);
                ldmx4(kfl, sKl + bo);
                mma16816(s[2*p],   qh[ks], &kfh[0]);
                mma16816(s[2*p],   qh[ks], &kfl[0]);
                mma16816(s[2*p],   ql[ks], &kfh[0]);
                mma16816(s[2*p+1], qh[ks], &kfh[2]);
                mma16816(s[2*p+1], qh[ks], &kfl[2]);
                mma16816(s[2*p+1], ql[ks], &kfh[2]);
            }
        }

        // scale + causal mask (diag tile only)
        bool diag = (kt == qt);
        int qrA = q0 + w*16 + (lane >> 2);
        #pragma unroll
        for (int nt = 0; nt < 8; nt++)
            #pragma unroll
            for (int e = 0; e < 4; e++) {
                float sv = s[nt][e] * 0.125f;
                if (diag) {
                    int col = kt*64 + nt*8 + 2*(lane & 3) + (e & 1);
                    int qr = qrA + ((e >> 1) << 3);
                    if (col > qr) sv = -1e30f;
                }
                s[nt][e] = sv;
            }

        // online softmax (rows A: regs 0,1; rows B: regs 2,3)
        float mx0 = -1e30f, mx1 = -1e30f;
        #pragma unroll
        for (int nt = 0; nt < 8; nt++) {
            mx0 = fmaxf(mx0, fmaxf(s[nt][0], s[nt][1]));
            mx1 = fmaxf(mx1, fmaxf(s[nt][2], s[nt][3]));
        }
        mx0 = fmaxf(mx0, __shfl_xor_sync(0xffffffffu, mx0, 1));
        mx0 = fmaxf(mx0, __shfl_xor_sync(0xffffffffu, mx0, 2));
        mx1 = fmaxf(mx1, __shfl_xor_sync(0xffffffffu, mx1, 1));
        mx1 = fmaxf(mx1, __shfl_xor_sync(0xffffffffu, mx1, 2));
        float mn0 = fmaxf(mrow0, mx0), mn1 = fmaxf(mrow1, mx1);
        float c0 = __expf(mrow0 - mn0), c1 = __expf(mrow1 - mn1);
        mrow0 = mn0; mrow1 = mn1;
        float rs0 = 0.0f, rs1 = 0.0f;
        #pragma unroll
        for (int nt = 0; nt < 8; nt++) {
            s[nt][0] = __expf(s[nt][0] - mn0); rs0 += s[nt][0];
            s[nt][1] = __expf(s[nt][1] - mn0); rs0 += s[nt][1];
            s[nt][2] = __expf(s[nt][2] - mn1); rs1 += s[nt][2];
            s[nt][3] = __expf(s[nt][3] - mn1); rs1 += s[nt][3];
        }
        rs0 += __shfl_xor_sync(0xffffffffu, rs0, 1);
        rs0 += __shfl_xor_sync(0xffffffffu, rs0, 2);
        rs1 += __shfl_xor_sync(0xffffffffu, rs1, 1);
        rs1 += __shfl_xor_sync(0xffffffffu, rs1, 2);
        lrow0 = lrow0 * c0 + rs0;
        lrow1 = lrow1 * c1 + rs1;
        #pragma unroll
        for (int dt = 0; dt < 8; dt++) {
            o[dt][0] *= c0; o[dt][1] *= c0;
            o[dt][2] *= c1; o[dt][3] *= c1;
        }

        // O += P V (bf16x3), P fragments built register-locally from score C-frags
        #pragma unroll
        for (int kc = 0; kc < 4; kc++) {
            uint32_t aph[4], apl[4];
            split2(s[2*kc][0],   s[2*kc][1],   aph[0], apl[0]);
            split2(s[2*kc][2],   s[2*kc][3],   aph[1], apl[1]);
            split2(s[2*kc+1][0], s[2*kc+1][1], aph[2], apl[2]);
            split2(s[2*kc+1][2], s[2*kc+1][3], aph[3], apl[3]);
            #pragma unroll
            for (int dt = 0; dt < 4; dt++) {
                uint32_t vfh[4], vfl[4];
                uint32_t vo = (uint32_t)((kc*16 + (lane & 15)) * ATS + dt*32 + (lane >> 4)*16);
                ldmx4t(vfh, sVh + vo);
                ldmx4t(vfl, sVl + vo);
                mma16816(o[2*dt],   aph, &vfh[0]);
                mma16816(o[2*dt],   aph, &vfl[0]);
                mma16816(o[2*dt],   apl, &vfh[0]);
                mma16816(o[2*dt+1], aph, &vfh[2]);
                mma16816(o[2*dt+1], aph, &vfl[2]);
                mma16816(o[2*dt+1], apl, &vfh[2]);
            }
        }
        __syncthreads();   // protect K/V smem before next iteration's loads
    }

    // epilogue: normalize + split-bf16 store
    float i0 = 1.0f / lrow0, i1 = 1.0f / lrow1;
    int qA = q0 + w*16 + (lane >> 2);
    size_t ob = ((size_t)b * SS) * QKV + h * HDIM;
    #pragma unroll
    for (int dt = 0; dt < 8; dt++) {
        int d = dt*8 + 2*(lane & 3);
        uint32_t hi, lo;
        float v0 = o[dt][0] * i0, v1 = o[dt][1] * i0;
        split2(v0, v1, hi, lo);
        size_t idxA = ob + (size_t)qA * QKV + d;
        *(uint32_t*)(Ohi + idxA) = hi;
        *(uint32_t*)(Olo + idxA) = lo;
        v0 = o[dt][2] * i1; v1 = o[dt][3] * i1;
        split2(v0, v1, hi, lo);
        size_t idxB = ob + (size_t)(qA + 8) * QKV + d;
        *(uint32_t*)(Ohi + idxB) = hi;
        *(uint32_t*)(Olo + idxB) = lo;
    }
}

// ---------------- fused residual add + LayerNorm (+ bf16 split) ----------------
__global__ void add_ln_kernel(float* __restrict__ h, const float* __restrict__ r,
                              const float* __restrict__ s, const float* __restrict__ b,
                              __nv_bfloat16* __restrict__ hh, __nv_bfloat16* __restrict__ hl) {
    __shared__ float red[12];
    int t = blockIdx.x;
    int d = threadIdx.x;
    int lane = d & 31, w = d >> 5;

    float v = h[(size_t)t*DM + d] + r[(size_t)t*DM + d];

    float sum = v;
    #pragma unroll
    for (int off = 16; off >= 1; off >>= 1) sum += __shfl_xor_sync(0xffffffffu, sum, off);
    if (lane == 0) red[w] = sum;
    __syncthreads();
    if (d == 0) { float tt = 0; for (int i = 0; i < 8; i++) tt += red[i]; red[8] = tt; }
    __syncthreads();
    float mean = red[8] * (1.0f/DM);

    float dv = v - mean;
    float sq = dv*dv;
    #pragma unroll
    for (int off = 16; off >= 1; off >>= 1) sq += __shfl_xor_sync(0xffffffffu, sq, off);
    if (lane == 0) red[w] = sq;
    __syncthreads();
    if (d == 0) { float tt = 0; for (int i = 0; i < 8; i++) tt += red[i]; red[9] = tt; }
    __syncthreads();
    float var = red[9] * (1.0f/DM);

    float out = dv * rsqrtf(var + 1e-5f) * s[d] + b[d];
    h[(size_t)t*DM + d] = out;
    __nv_bfloat16 hi, lo; split_bf16(out, hi, lo);
    hh[(size_t)t*DM + d] = hi;
    hl[(size_t)t*DM + d] = lo;
}

// ---------------- launch ----------------
extern "C" void kernel_launch(void* const* d_in, const int* in_sizes, int n_in,
                              void* d_out, int out_size) {
    (void)in_sizes; (void)n_in; (void)out_size;
    const int*   x    = (const int*)  d_in[0];
    const float* emb  = (const float*)d_in[1];
    const float* wq   = (const float*)d_in[2];
    const float* bq   = (const float*)d_in[3];
    const float* wk   = (const float*)d_in[4];
    const float* bk   = (const float*)d_in[5];
    const float* wv   = (const float*)d_in[6];
    const float* bv   = (const float*)d_in[7];
    const float* wo   = (const float*)d_in[8];
    const float* bo   = (const float*)d_in[9];
    const float* ln1s = (const float*)d_in[10];
    const float* ln1b = (const float*)d_in[11];
    const float* w1   = (const float*)d_in[12];
    const float* b1   = (const float*)d_in[13];
    const float* w2   = (const float*)d_in[14];
    const float* b2   = (const float*)d_in[15];
    const float* ln2s = (const float*)d_in[16];
    const float* ln2b = (const float*)d_in[17];
    const float* ow   = (const float*)d_in[18];
    const float* ob   = (const float*)d_in[19];
    float* out = (float*)d_out;

    float *h, *p, *pe, *bqkv;
    __nv_bfloat16 *hh, *hl, *qkvh, *qkvl, *ohi, *olo, *ffh, *ffl, *wth, *wtl;
    cudaGetSymbolAddress((void**)&h,    g_h);
    cudaGetSymbolAddress((void**)&p,    g_p);
    cudaGetSymbolAddress((void**)&pe,   g_pe);
    cudaGetSymbolAddress((void**)&bqkv, g_bqkv);
    cudaGetSymbolAddress((void**)&hh,   g_hh);
    cudaGetSymbolAddress((void**)&hl,   g_hl);
    cudaGetSymbolAddress((void**)&qkvh, g_qkvh);
    cudaGetSymbolAddress((void**)&qkvl, g_qkvl);
    cudaGetSymbolAddress((void**)&ohi,  g_ohi);
    cudaGetSymbolAddress((void**)&olo,  g_olo);
    cudaGetSymbolAddress((void**)&ffh,  g_ffh);
    cudaGetSymbolAddress((void**)&ffl,  g_ffl);
    cudaGetSymbolAddress((void**)&wth,  g_wth);
    cudaGetSymbolAddress((void**)&wtl,  g_wtl);

    static int attr_set = 0;
    if (!attr_set) {
        cudaFuncSetAttribute(gemm_mma, cudaFuncAttributeMaxDynamicSharedMemorySize, GSMEM);
        cudaFuncSetAttribute(attn_mma, cudaFuncAttributeMaxDynamicSharedMemorySize, ASMEM);
        attr_set = 1;
    }

    dim3 wblk(32, 8);
    wsplit<<<dim3(DM/32,  QKV/32,  NLAYER), wblk>>>(wq, wth + 0,      wtl + 0,      DM,  QKV,  (size_t)DM*QKV,  1048576);
    wsplit<<<dim3(DM/32,  QKV/32,  NLAYER), wblk>>>(wk, wth + 131072, wtl + 131072, DM,  QKV,  (size_t)DM*QKV,  1048576);
    wsplit<<<dim3(DM/32,  QKV/32,  NLAYER), wblk>>>(wv, wth + 262144, wtl + 262144, DM,  QKV,  (size_t)DM*QKV,  1048576);
    wsplit<<<dim3(QKV/32, DM/32,   NLAYER), wblk>>>(wo, wth + 393216, wtl + 393216, QKV, DM,   (size_t)QKV*DM,  1048576);
    wsplit<<<dim3(DM/32,  FFD/32,  NLAYER), wblk>>>(w1, wth + 524288, wtl + 524288, DM,  FFD,  (size_t)DM*FFD,  1048576);
    wsplit<<<dim3(FFD/32, DM/32,   NLAYER), wblk>>>(w2, wth + 786432, wtl + 786432, FFD, DM,   (size_t)FFD*DM,  1048576);
    wsplit<<<dim3(DM/32,  OUTD/32, 1),      wblk>>>(ow, wth + OWT,    wtl + OWT,    DM,  OUTD, 0, 0);
    pack_bias<<<NLAYER, 512>>>(bq, bk, bv, bqkv);

    pe_kernel   <<<SS, DM>>>(pe);
    embed_kernel<<<NT, DM>>>(x, emb, pe, h, hh, hl);

    for (int i = 0; i < NLAYER; i++) {
        gemm_mma<<<dim3(1536/GBN, NT/GBM), 256, GSMEM>>>(hh, hl, wth + WQT(i), wtl + WQT(i),
                                                         bqkv + i*1536, 0, qkvh, qkvl, 1536, DM, 1, 0);
        attn_mma<<<dim3(SS/64, NB*NH), 128, ASMEM>>>(qkvh, qkvl, ohi, olo);
        gemm_mma<<<dim3(DM/GBN, NT/GBM), 256, GSMEM>>>(ohi, olo, wth + WOT(i), wtl + WOT(i),
                                                       bo + i*DM, p, 0, 0, DM, QKV, 0, 0);
        add_ln_kernel<<<NT, DM>>>(h, p, ln1s + i*DM, ln1b + i*DM, hh, hl);
        gemm_mma<<<dim3(FFD/GBN, NT/GBM), 256, GSMEM>>>(hh, hl, wth + W1T(i), wtl + W1T(i),
                                                        b1 + i*FFD, 0, ffh, ffl, FFD, DM, 1, 1);
        gemm_mma<<<dim3(DM/GBN, NT/GBM), 256, GSMEM>>>(ffh, ffl, wth + W2T(i), wtl + W2T(i),
                                                       b2 + i*DM, p, 0, 0, DM, FFD, 0, 0);
        add_ln_kernel<<<NT, DM>>>(h, p, ln2s + i*DM, ln2b + i*DM, hh, hl);
    }

    gemm_mma<<<dim3(OUTD/GBN, NT/GBM), 256, GSMEM>>>(hh, hl, wth + OWT, wtl + OWT,
                                                     ob, out, 0, 0, OUTD, DM, 0, 0);
}

// round 8
// speedup vs baseline: 1.4909x; 1.4909x over previous
#include <cuda_runtime.h>
#include <cuda_bf16.h>
#include <math.h>
#include <stdint.h>

#define NB 32
#define SS 512
#define DM 256
#define NH 8
#define HDIM 64
#define NLAYER 5
#define FFD 1024
#define OUTD 4096
#define NT (NB*SS)     /* 16384 tokens */
#define QKV 512        /* H*HD */

// ---------------- scratch (no allocations allowed) ----------------
__device__ float g_h [NT*DM];
__device__ float g_p [NT*DM];
__device__ float g_pe[SS*DM];
__device__ float g_bqkv[NLAYER*1536];
__device__ __nv_bfloat16 g_hh [NT*DM];
__device__ __nv_bfloat16 g_hl [NT*DM];
__device__ __nv_bfloat16 g_qkvh[NT*1536];
__device__ __nv_bfloat16 g_qkvl[NT*1536];
__device__ __nv_bfloat16 g_ohi[NT*QKV];
__device__ __nv_bfloat16 g_olo[NT*QKV];
__device__ __nv_bfloat16 g_ffh[NT*FFD];
__device__ __nv_bfloat16 g_ffl[NT*FFD];
#define WT_TOTAL 6291456
__device__ __nv_bfloat16 g_wth[WT_TOTAL];
__device__ __nv_bfloat16 g_wtl[WT_TOTAL];

// weight-transpose offsets (elements); wq/wk/wv contiguous per layer -> fused QKV B
#define WQT(i) ((size_t)(i)*1048576)
#define WOT(i) (WQT(i)+393216)
#define W1T(i) (WQT(i)+524288)
#define W2T(i) (WQT(i)+786432)
#define OWT    ((size_t)5242880)

// ---------------- helpers ----------------
__device__ __forceinline__ uint32_t smem_u32(const void* p) {
    uint32_t a;
    asm("{ .reg .u64 t; cvta.to.shared.u64 t, %1; cvt.u32.u64 %0, t; }" : "=r"(a) : "l"(p));
    return a;
}
__device__ __forceinline__ void split_bf16(float v, __nv_bfloat16& hi, __nv_bfloat16& lo) {
    hi = __float2bfloat16(v);
    lo = __float2bfloat16(v - __bfloat162float(hi));
}
__device__ __forceinline__ void split2(float a, float b, uint32_t& hi, uint32_t& lo) {
    __nv_bfloat16 ha = __float2bfloat16(a), hb = __float2bfloat16(b);
    __nv_bfloat16 la = __float2bfloat16(a - __bfloat162float(ha));
    __nv_bfloat16 lb = __float2bfloat16(b - __bfloat162float(hb));
    __nv_bfloat162 ph; ph.x = ha; ph.y = hb;
    __nv_bfloat162 pl; pl.x = la; pl.y = lb;
    hi = *(uint32_t*)&ph; lo = *(uint32_t*)&pl;
}
__device__ __forceinline__ void cp16(uint32_t dst, const void* src) {
    asm volatile("cp.async.cg.shared.global [%0], [%1], 16;" :: "r"(dst), "l"(src));
}
__device__ __forceinline__ void ldmx4(uint32_t* r, uint32_t addr) {
    asm volatile("ldmatrix.sync.aligned.m8n8.x4.shared.b16 {%0,%1,%2,%3}, [%4];"
        : "=r"(r[0]), "=r"(r[1]), "=r"(r[2]), "=r"(r[3]) : "r"(addr));
}
__device__ __forceinline__ void ldmx4t(uint32_t* r, uint32_t addr) {
    asm volatile("ldmatrix.sync.aligned.m8n8.x4.trans.shared.b16 {%0,%1,%2,%3}, [%4];"
        : "=r"(r[0]), "=r"(r[1]), "=r"(r[2]), "=r"(r[3]) : "r"(addr));
}
__device__ __forceinline__ void mma16816(float* d, const uint32_t* a, const uint32_t* b) {
    asm volatile("mma.sync.aligned.m16n8k16.row.col.f32.bf16.bf16.f32 "
        "{%0,%1,%2,%3}, {%4,%5,%6,%7}, {%8,%9}, {%0,%1,%2,%3};"
        : "+f"(d[0]), "+f"(d[1]), "+f"(d[2]), "+f"(d[3])
        : "r"(a[0]), "r"(a[1]), "r"(a[2]), "r"(a[3]), "r"(b[0]), "r"(b[1]));
}

// ---------------- positional encoding ----------------
__global__ void pe_kernel(float* __restrict__ pe) {
    int s = blockIdx.x, d = threadIdx.x;
    int i = d >> 1;
    float div = powf(10000.0f, (float)(2*i) / (float)DM);
    float ang = (float)s / div;
    pe[s*DM + d] = (d & 1) ? cosf(ang) : sinf(ang);
}

// ---------------- embedding + PE (+ bf16 split) ----------------
__global__ void embed_kernel(const int* __restrict__ x, const float* __restrict__ emb,
                             const float* __restrict__ pe, float* __restrict__ h,
                             __nv_bfloat16* __restrict__ hh, __nv_bfloat16* __restrict__ hl) {
    int t = blockIdx.x, d = threadIdx.x;
    int tok = x[t];
    int s = t & (SS-1);
    float v = emb[tok*DM + d] + pe[s*DM + d];
    h[(size_t)t*DM + d] = v;
    __nv_bfloat16 hi, lo; split_bf16(v, hi, lo);
    hh[(size_t)t*DM + d] = hi;
    hl[(size_t)t*DM + d] = lo;
}

// ---------------- pack QKV biases: [NL][1536] ----------------
__global__ void pack_bias(const float* __restrict__ bq, const float* __restrict__ bk,
                          const float* __restrict__ bv, float* __restrict__ out) {
    int i = blockIdx.x, d = threadIdx.x;
    out[i*1536 + d]        = bq[i*QKV + d];
    out[i*1536 + 512 + d]  = bk[i*QKV + d];
    out[i*1536 + 1024 + d] = bv[i*QKV + d];
}

// ---------------- weight transpose + split (layer-batched) ----------------
__global__ void wsplit(const float* __restrict__ W, __nv_bfloat16* __restrict__ Thi,
                       __nv_bfloat16* __restrict__ Tlo, int K, int N,
                       size_t lsrc, size_t ldst) {
    __shared__ float t[32][33];
    const float* Ws = W + (size_t)blockIdx.z * lsrc;
    __nv_bfloat16* Th = Thi + (size_t)blockIdx.z * ldst;
    __nv_bfloat16* Tl = Tlo + (size_t)blockIdx.z * ldst;
    int k0 = blockIdx.x*32, n0 = blockIdx.y*32;
    int tx = threadIdx.x, ty = threadIdx.y;  // 32 x 8
    #pragma unroll
    for (int i = 0; i < 32; i += 8)
        t[ty+i][tx] = Ws[(size_t)(k0+ty+i)*N + n0+tx];
    __syncthreads();
    #pragma unroll
    for (int i = 0; i < 32; i += 8) {
        float v = t[tx][ty+i];
        __nv_bfloat16 hi, lo; split_bf16(v, hi, lo);
        Th[(size_t)(n0+ty+i)*K + k0+tx] = hi;
        Tl[(size_t)(n0+ty+i)*K + k0+tx] = lo;
    }
}

// ---------------- HMMA bf16x3 GEMM ----------------
#define GBM 128
#define GBN 128
#define GBK 32
#define ROWB 80
#define TILEB (128*ROWB)
#define OFF_AHI 0
#define OFF_ALO TILEB
#define OFF_BHI (2*TILEB)
#define OFF_BLO (3*TILEB)
#define STAGEB (4*TILEB)
#define GSMEM (2*STAGEB)

__global__ void __launch_bounds__(256, 1)
gemm_mma(const __nv_bfloat16* __restrict__ Ahi, const __nv_bfloat16* __restrict__ Alo,
         const __nv_bfloat16* __restrict__ Bhi, const __nv_bfloat16* __restrict__ Blo,
         const float* __restrict__ bias,
         float* __restrict__ Cf, __nv_bfloat16* __restrict__ Chi, __nv_bfloat16* __restrict__ Clo,
         int Ncols, int K, int mode, int relu) {
    extern __shared__ char smem[];
    uint32_t sb = smem_u32(smem);
    int tid = threadIdx.x;
    int lane = tid & 31;
    int wid = tid >> 5;
    int warp_m = wid & 1;
    int warp_n = wid >> 1;
    int row0 = blockIdx.y * GBM;
    int col0 = blockIdx.x * GBN;

    int lr  = tid >> 2;
    int lc  = tid & 3;
    uint32_t sm_off0 = (uint32_t)(lr * ROWB + lc * 16);
    uint32_t sm_off1 = (uint32_t)((lr + 64) * ROWB + lc * 16);

#define LOAD_STAGE(bufidx, chunk) do { \
    uint32_t so = sb + (uint32_t)(bufidx)*STAGEB; \
    int kc = (chunk)*GBK + lc*8; \
    size_t ga0 = (size_t)(row0 + lr)      * K + kc; \
    size_t ga1 = (size_t)(row0 + lr + 64) * K + kc; \
    size_t gb0 = (size_t)(col0 + lr)      * K + kc; \
    size_t gb1 = (size_t)(col0 + lr + 64) * K + kc; \
    cp16(so + OFF_AHI + sm_off0, Ahi + ga0); \
    cp16(so + OFF_AHI + sm_off1, Ahi + ga1); \
    cp16(so + OFF_ALO + sm_off0, Alo + ga0); \
    cp16(so + OFF_ALO + sm_off1, Alo + ga1); \
    cp16(so + OFF_BHI + sm_off0, Bhi + gb0); \
    cp16(so + OFF_BHI + sm_off1, Bhi + gb1); \
    cp16(so + OFF_BLO + sm_off0, Blo + gb0); \
    cp16(so + OFF_BLO + sm_off1, Blo + gb1); \
} while(0)

    uint32_t a_row = (uint32_t)(warp_m*64 + (lane & 15));
    uint32_t a_off = a_row * ROWB + ((uint32_t)(lane >> 4)) * 16;
    uint32_t b_row = (uint32_t)(warp_n*32 + (lane & 7) + ((lane >> 4) << 3));
    uint32_t b_off = b_row * ROWB + ((uint32_t)((lane >> 3) & 1)) * 16;

    float acc[4][4][4];
    #pragma unroll
    for (int i = 0; i < 4; i++)
        #pragma unroll
        for (int j = 0; j < 4; j++)
            #pragma unroll
            for (int e = 0; e < 4; e++) acc[i][j][e] = 0.0f;

    int nch = K / GBK;
    LOAD_STAGE(0, 0);
    asm volatile("cp.async.commit_group;" ::: "memory");

    for (int c = 0; c < nch; c++) {
        int buf = c & 1;
        asm volatile("cp.async.wait_group 0;" ::: "memory");
        __syncthreads();
        if (c + 1 < nch) {
            LOAD_STAGE((c + 1) & 1, c + 1);
            asm volatile("cp.async.commit_group;" ::: "memory");
        }

        uint32_t so = sb + (uint32_t)buf * STAGEB;
        #pragma unroll
        for (int s = 0; s < 2; s++) {
            uint32_t ks = (uint32_t)(s * 32);
            uint32_t ah[4][4], al[4][4];
            #pragma unroll
            for (int mi = 0; mi < 4; mi++) {
                uint32_t ao = a_off + (uint32_t)(mi*16) * ROWB + ks;
                ldmx4(ah[mi], so + OFF_AHI + ao);
                ldmx4(al[mi], so + OFF_ALO + ao);
            }
            uint32_t bh[2][4], bl[2][4];
            #pragma unroll
            for (int nt = 0; nt < 2; nt++) {
                uint32_t bo = b_off + (uint32_t)(nt*16) * ROWB + ks;
                ldmx4(bh[nt], so + OFF_BHI + bo);
                ldmx4(bl[nt], so + OFF_BLO + bo);
            }
            #pragma unroll
            for (int mi = 0; mi < 4; mi++)
                #pragma unroll
                for (int nj = 0; nj < 4; nj++) {
                    const uint32_t* ph = &bh[nj >> 1][(nj & 1) * 2];
                    const uint32_t* pl = &bl[nj >> 1][(nj & 1) * 2];
                    mma16816(acc[mi][nj], ah[mi], ph);
                    mma16816(acc[mi][nj], ah[mi], pl);
                    mma16816(acc[mi][nj], al[mi], ph);
                }
        }
        __syncthreads();
    }

    int em = row0 + warp_m*64 + (lane >> 2);
    int en = col0 + warp_n*32 + (lane & 3) * 2;
    #pragma unroll
    for (int mi = 0; mi < 4; mi++) {
        #pragma unroll
        for (int nj = 0; nj < 4; nj++) {
            int cc = en + nj*8;
            float b0 = bias[cc], b1 = bias[cc + 1];
            #pragma unroll
            for (int half = 0; half < 2; half++) {
                int rr = em + mi*16 + half*8;
                float v0 = acc[mi][nj][half*2 + 0] + b0;
                float v1 = acc[mi][nj][half*2 + 1] + b1;
                if (relu) { v0 = fmaxf(v0, 0.0f); v1 = fmaxf(v1, 0.0f); }
                size_t idx = (size_t)rr * Ncols + cc;
                if (mode == 0) {
                    *(float2*)(Cf + idx) = make_float2(v0, v1);
                } else {
                    uint32_t hi, lo;
                    split2(v0, v1, hi, lo);
                    *(uint32_t*)(Chi + idx) = hi;
                    *(uint32_t*)(Clo + idx) = lo;
                }
            }
        }
    }
#undef LOAD_STAGE
}

// ---------------- HMMA flash attention (bf16x3, 128 queries/CTA, double-buffered K/V) ----------------
// grid (SS/128, B*H), 256 threads (8 warps x m16). QKV packed [t][1536] hi/lo.
#define ATS 144                 /* bytes per 64-bf16 row (128 data + 16 pad) */
#define ATILE (64*ATS)          /* 9216 */
#define ASTAGE (4*ATILE)        /* Khi,Klo,Vhi,Vlo = 36864 */
#define ASMEM (2*ASTAGE)        /* 73728 */

__global__ void __launch_bounds__(256, 2)
attn_mma(const __nv_bfloat16* __restrict__ Xh, const __nv_bfloat16* __restrict__ Xl,
         __nv_bfloat16* __restrict__ Ohi, __nv_bfloat16* __restrict__ Olo) {
    extern __shared__ char smem[];
    uint32_t sb = smem_u32(smem);

    int tid = threadIdx.x, lane = tid & 31, w = tid >> 5;
    int qt = blockIdx.x, bh = blockIdx.y;
    int b = bh >> 3, h = bh & 7;
    int q0 = qt * 128;
    size_t gq = ((size_t)b * SS) * 1536 + h * HDIM;

    // ---- load Q (128 rows, hi/lo) into stage-0 region temporarily ----
    // Qhi rows r at sb + r*ATS (tiles 0-1), Qlo rows r at sb + 2*ATILE + r*ATS (tiles 2-3)
    {
        int r = tid >> 1, cg = (tid & 1) * 4;
        size_t go = gq + (size_t)(q0 + r) * 1536 + cg * 8;
        uint32_t so = (uint32_t)(r * ATS + cg * 16);
        #pragma unroll
        for (int c = 0; c < 4; c++) {
            cp16(sb + so + c*16, Xh + go + c*8);
            cp16(sb + 2*ATILE + so + c*16, Xl + go + c*8);
        }
    }
    asm volatile("cp.async.commit_group;" ::: "memory");
    asm volatile("cp.async.wait_group 0;" ::: "memory");
    __syncthreads();

    uint32_t qh[4][4], ql[4][4];
    #pragma unroll
    for (int ks = 0; ks < 4; ks++) {
        uint32_t ao = (uint32_t)((w*16 + (lane & 15)) * ATS + (lane >> 4)*16 + ks*32);
        ldmx4(qh[ks], sb + ao);
        ldmx4(ql[ks], sb + 2*ATILE + ao);
    }
    __syncthreads();   // all warps done reading Q before stage-0 K/V overwrites

    // ---- K/V stage loader ----
#define LOADKV(stage, kt) do { \
    int quad = tid >> 6, r = tid & 63; \
    const __nv_bfloat16* src = (quad == 0 || quad == 2) ? Xh : Xl; \
    int coladd = (quad < 2) ? 512 : 1024; \
    size_t go = gq + (size_t)((kt)*64 + r) * 1536 + coladd; \
    uint32_t dst = sb + (uint32_t)(stage)*ASTAGE + (uint32_t)quad*ATILE + (uint32_t)(r * ATS); \
    _Pragma("unroll") \
    for (int c = 0; c < 8; c++) cp16(dst + c*16, src + go + c*8); \
} while(0)

    float mrow0 = -1e30f, mrow1 = -1e30f, lrow0 = 0.0f, lrow1 = 0.0f;
    float o[8][4];
    #pragma unroll
    for (int dt = 0; dt < 8; dt++)
        #pragma unroll
        for (int e = 0; e < 4; e++) o[dt][e] = 0.0f;

    int ktmax = 2*qt + 1;
    LOADKV(0, 0);
    asm volatile("cp.async.commit_group;" ::: "memory");

    int qrA = q0 + w*16 + (lane >> 2);

    for (int kt = 0; kt <= ktmax; kt++) {
        if (kt < ktmax) {
            LOADKV((kt + 1) & 1, kt + 1);
            asm volatile("cp.async.commit_group;" ::: "memory");
            asm volatile("cp.async.wait_group 1;" ::: "memory");
        } else {
            asm volatile("cp.async.wait_group 0;" ::: "memory");
        }
        __syncthreads();

        uint32_t so = sb + (uint32_t)(kt & 1) * ASTAGE;
        uint32_t sKh = so, sKl = so + ATILE, sVh = so + 2*ATILE, sVl = so + 3*ATILE;

        // scores S = Q K^T (bf16x3)
        float s[8][4];
        #pragma unroll
        for (int nt = 0; nt < 8; nt++)
            #pragma unroll
            for (int e = 0; e < 4; e++) s[nt][e] = 0.0f;

        #pragma unroll
        for (int p = 0; p < 4; p++) {
            #pragma unroll
            for (int ks = 0; ks < 4; ks++) {
                uint32_t kfh[4], kfl[4];
                uint32_t bo = (uint32_t)((p*16 + (lane & 7) + ((lane >> 4) << 3)) * ATS
                                         + ((lane >> 3) & 1)*16 + ks*32);
                ldmx4(kfh, sKh + bo);
                ldmx4(kfl, sKl + bo);
                mma16816(s[2*p],   qh[ks], &kfh[0]);
                mma16816(s[2*p],   qh[ks], &kfl[0]);
                mma16816(s[2*p],   ql[ks], &kfh[0]);
                mma16816(s[2*p+1], qh[ks], &kfh[2]);
                mma16816(s[2*p+1], qh[ks], &kfl[2]);
                mma16816(s[2*p+1], ql[ks], &kfh[2]);
            }
        }

        // scale + causal mask (always applied; kt can exceed this warp's diagonal)
        #pragma unroll
        for (int nt = 0; nt < 8; nt++)
            #pragma unroll
            for (int e = 0; e < 4; e++) {
                float sv = s[nt][e] * 0.125f;
                int col = kt*64 + nt*8 + 2*(lane & 3) + (e & 1);
                int qr = qrA + ((e >> 1) << 3);
                if (col > qr) sv = -1e30f;
                s[nt][e] = sv;
            }

        // online softmax (rows A: regs 0,1; rows B: regs 2,3)
        float mx0 = -1e30f, mx1 = -1e30f;
        #pragma unroll
        for (int nt = 0; nt < 8; nt++) {
            mx0 = fmaxf(mx0, fmaxf(s[nt][0], s[nt][1]));
            mx1 = fmaxf(mx1, fmaxf(s[nt][2], s[nt][3]));
        }
        mx0 = fmaxf(mx0, __shfl_xor_sync(0xffffffffu, mx0, 1));
        mx0 = fmaxf(mx0, __shfl_xor_sync(0xffffffffu, mx0, 2));
        mx1 = fmaxf(mx1, __shfl_xor_sync(0xffffffffu, mx1, 1));
        mx1 = fmaxf(mx1, __shfl_xor_sync(0xffffffffu, mx1, 2));
        float mn0 = fmaxf(mrow0, mx0), mn1 = fmaxf(mrow1, mx1);
        float c0 = __expf(mrow0 - mn0), c1 = __expf(mrow1 - mn1);
        mrow0 = mn0; mrow1 = mn1;
        float rs0 = 0.0f, rs1 = 0.0f;
        #pragma unroll
        for (int nt = 0; nt < 8; nt++) {
            s[nt][0] = __expf(s[nt][0] - mn0); rs0 += s[nt][0];
            s[nt][1] = __expf(s[nt][1] - mn0); rs0 += s[nt][1];
            s[nt][2] = __expf(s[nt][2] - mn1); rs1 += s[nt][2];
            s[nt][3] = __expf(s[nt][3] - mn1); rs1 += s[nt][3];
        }
        rs0 += __shfl_xor_sync(0xffffffffu, rs0, 1);
        rs0 += __shfl_xor_sync(0xffffffffu, rs0, 2);
        rs1 += __shfl_xor_sync(0xffffffffu, rs1, 1);
        rs1 += __shfl_xor_sync(0xffffffffu, rs1, 2);
        lrow0 = lrow0 * c0 + rs0;
        lrow1 = lrow1 * c1 + rs1;
        #pragma unroll
        for (int dt = 0; dt < 8; dt++) {
            o[dt][0] *= c0; o[dt][1] *= c0;
            o[dt][2] *= c1; o[dt][3] *= c1;
        }

        // O += P V (bf16x3), P fragments built register-locally from score C-frags
        #pragma unroll
        for (int kc = 0; kc < 4; kc++) {
            uint32_t aph[4], apl[4];
            split2(s[2*kc][0],   s[2*kc][1],   aph[0], apl[0]);
            split2(s[2*kc][2],   s[2*kc][3],   aph[1], apl[1]);
            split2(s[2*kc+1][0], s[2*kc+1][1], aph[2], apl[2]);
            split2(s[2*kc+1][2], s[2*kc+1][3], aph[3], apl[3]);
            #pragma unroll
            for (int dt = 0; dt < 4; dt++) {
                uint32_t vfh[4], vfl[4];
                uint32_t vo = (uint32_t)((kc*16 + (lane & 15)) * ATS + dt*32 + (lane >> 4)*16);
                ldmx4t(vfh, sVh + vo);
                ldmx4t(vfl, sVl + vo);
                mma16816(o[2*dt],   aph, &vfh[0]);
                mma16816(o[2*dt],   aph, &vfl[0]);
                mma16816(o[2*dt],   apl, &vfh[0]);
                mma16816(o[2*dt+1], aph, &vfh[2]);
                mma16816(o[2*dt+1], aph, &vfl[2]);
                mma16816(o[2*dt+1], apl, &vfh[2]);
            }
        }
        __syncthreads();   // compute done before next stage load overwrites
    }

    // epilogue: normalize + split-bf16 store
    float i0 = 1.0f / lrow0, i1 = 1.0f / lrow1;
    int qA = q0 + w*16 + (lane >> 2);
    size_t ob = ((size_t)b * SS) * QKV + h * HDIM;
    #pragma unroll
    for (int dt = 0; dt < 8; dt++) {
        int d = dt*8 + 2*(lane & 3);
        uint32_t hi, lo;
        float v0 = o[dt][0] * i0, v1 = o[dt][1] * i0;
        split2(v0, v1, hi, lo);
        size_t idxA = ob + (size_t)qA * QKV + d;
        *(uint32_t*)(Ohi + idxA) = hi;
        *(uint32_t*)(Olo + idxA) = lo;
        v0 = o[dt][2] * i1; v1 = o[dt][3] * i1;
        split2(v0, v1, hi, lo);
        size_t idxB = ob + (size_t)(qA + 8) * QKV + d;
        *(uint32_t*)(Ohi + idxB) = hi;
        *(uint32_t*)(Olo + idxB) = lo;
    }
#undef LOADKV
}

// ---------------- fused residual add + LayerNorm (+ bf16 split) ----------------
__global__ void add_ln_kernel(float* __restrict__ h, const float* __restrict__ r,
                              const float* __restrict__ s, const float* __restrict__ b,
                              __nv_bfloat16* __restrict__ hh, __nv_bfloat16* __restrict__ hl) {
    __shared__ float red[12];
    int t = blockIdx.x;
    int d = threadIdx.x;
    int lane = d & 31, w = d >> 5;

    float v = h[(size_t)t*DM + d] + r[(size_t)t*DM + d];

    float sum = v;
    #pragma unroll
    for (int off = 16; off >= 1; off >>= 1) sum += __shfl_xor_sync(0xffffffffu, sum, off);
    if (lane == 0) red[w] = sum;
    __syncthreads();
    if (d == 0) { float tt = 0; for (int i = 0; i < 8; i++) tt += red[i]; red[8] = tt; }
    __syncthreads();
    float mean = red[8] * (1.0f/DM);

    float dv = v - mean;
    float sq = dv*dv;
    #pragma unroll
    for (int off = 16; off >= 1; off >>= 1) sq += __shfl_xor_sync(0xffffffffu, sq, off);
    if (lane == 0) red[w] = sq;
    __syncthreads();
    if (d == 0) { float tt = 0; for (int i = 0; i < 8; i++) tt += red[i]; red[9] = tt; }
    __syncthreads();
    float var = red[9] * (1.0f/DM);

    float out = dv * rsqrtf(var + 1e-5f) * s[d] + b[d];
    h[(size_t)t*DM + d] = out;
    __nv_bfloat16 hi, lo; split_bf16(out, hi, lo);
    hh[(size_t)t*DM + d] = hi;
    hl[(size_t)t*DM + d] = lo;
}

// ---------------- launch ----------------
extern "C" void kernel_launch(void* const* d_in, const int* in_sizes, int n_in,
                              void* d_out, int out_size) {
    (void)in_sizes; (void)n_in; (void)out_size;
    const int*   x    = (const int*)  d_in[0];
    const float* emb  = (const float*)d_in[1];
    const float* wq   = (const float*)d_in[2];
    const float* bq   = (const float*)d_in[3];
    const float* wk   = (const float*)d_in[4];
    const float* bk   = (const float*)d_in[5];
    const float* wv   = (const float*)d_in[6];
    const float* bv   = (const float*)d_in[7];
    const float* wo   = (const float*)d_in[8];
    const float* bo   = (const float*)d_in[9];
    const float* ln1s = (const float*)d_in[10];
    const float* ln1b = (const float*)d_in[11];
    const float* w1   = (const float*)d_in[12];
    const float* b1   = (const float*)d_in[13];
    const float* w2   = (const float*)d_in[14];
    const float* b2   = (const float*)d_in[15];
    const float* ln2s = (const float*)d_in[16];
    const float* ln2b = (const float*)d_in[17];
    const float* ow   = (const float*)d_in[18];
    const float* ob   = (const float*)d_in[19];
    float* out = (float*)d_out;

    float *h, *p, *pe, *bqkv;
    __nv_bfloat16 *hh, *hl, *qkvh, *qkvl, *ohi, *olo, *ffh, *ffl, *wth, *wtl;
    cudaGetSymbolAddress((void**)&h,    g_h);
    cudaGetSymbolAddress((void**)&p,    g_p);
    cudaGetSymbolAddress((void**)&pe,   g_pe);
    cudaGetSymbolAddress((void**)&bqkv, g_bqkv);
    cudaGetSymbolAddress((void**)&hh,   g_hh);
    cudaGetSymbolAddress((void**)&hl,   g_hl);
    cudaGetSymbolAddress((void**)&qkvh, g_qkvh);
    cudaGetSymbolAddress((void**)&qkvl, g_qkvl);
    cudaGetSymbolAddress((void**)&ohi,  g_ohi);
    cudaGetSymbolAddress((void**)&olo,  g_olo);
    cudaGetSymbolAddress((void**)&ffh,  g_ffh);
    cudaGetSymbolAddress((void**)&ffl,  g_ffl);
    cudaGetSymbolAddress((void**)&wth,  g_wth);
    cudaGetSymbolAddress((void**)&wtl,  g_wtl);

    static int attr_set = 0;
    if (!attr_set) {
        cudaFuncSetAttribute(gemm_mma, cudaFuncAttributeMaxDynamicSharedMemorySize, GSMEM);
        cudaFuncSetAttribute(attn_mma, cudaFuncAttributeMaxDynamicSharedMemorySize, ASMEM);
        attr_set = 1;
    }

    dim3 wblk(32, 8);
    wsplit<<<dim3(DM/32,  QKV/32,  NLAYER), wblk>>>(wq, wth + 0,      wtl + 0,      DM,  QKV,  (size_t)DM*QKV,  1048576);
    wsplit<<<dim3(DM/32,  QKV/32,  NLAYER), wblk>>>(wk, wth + 131072, wtl + 131072, DM,  QKV,  (size_t)DM*QKV,  1048576);
    wsplit<<<dim3(DM/32,  QKV/32,  NLAYER), wblk>>>(wv, wth + 262144, wtl + 262144, DM,  QKV,  (size_t)DM*QKV,  1048576);
    wsplit<<<dim3(QKV/32, DM/32,   NLAYER), wblk>>>(wo, wth + 393216, wtl + 393216, QKV, DM,   (size_t)QKV*DM,  1048576);
    wsplit<<<dim3(DM/32,  FFD/32,  NLAYER), wblk>>>(w1, wth + 524288, wtl + 524288, DM,  FFD,  (size_t)DM*FFD,  1048576);
    wsplit<<<dim3(FFD/32, DM/32,   NLAYER), wblk>>>(w2, wth + 786432, wtl + 786432, FFD, DM,   (size_t)FFD*DM,  1048576);
    wsplit<<<dim3(DM/32,  OUTD/32, 1),      wblk>>>(ow, wth + OWT,    wtl + OWT,    DM,  OUTD, 0, 0);
    pack_bias<<<NLAYER, 512>>>(bq, bk, bv, bqkv);

    pe_kernel   <<<SS, DM>>>(pe);
    embed_kernel<<<NT, DM>>>(x, emb, pe, h, hh, hl);

    for (int i = 0; i < NLAYER; i++) {
        gemm_mma<<<dim3(1536/GBN, NT/GBM), 256, GSMEM>>>(hh, hl, wth + WQT(i), wtl + WQT(i),
                                                         bqkv + i*1536, 0, qkvh, qkvl, 1536, DM, 1, 0);
        attn_mma<<<dim3(SS/128, NB*NH), 256, ASMEM>>>(qkvh, qkvl, ohi, olo);
        gemm_mma<<<dim3(DM/GBN, NT/GBM), 256, GSMEM>>>(ohi, olo, wth + WOT(i), wtl + WOT(i),
                                                       bo + i*DM, p, 0, 0, DM, QKV, 0, 0);
        add_ln_kernel<<<NT, DM>>>(h, p, ln1s + i*DM, ln1b + i*DM, hh, hl);
        gemm_mma<<<dim3(FFD/GBN, NT/GBM), 256, GSMEM>>>(hh, hl, wth + W1T(i), wtl + W1T(i),
                                                        b1 + i*FFD, 0, ffh, ffl, FFD, DM, 1, 1);
        gemm_mma<<<dim3(DM/GBN, NT/GBM), 256, GSMEM>>>(ffh, ffl, wth + W2T(i), wtl + W2T(i),
                                                       b2 + i*DM, p, 0, 0, DM, FFD, 0, 0);
        add_ln_kernel<<<NT, DM>>>(h, p, ln2s + i*DM, ln2b + i*DM, hh, hl);
    }

    gemm_mma<<<dim3(OUTD/GBN, NT/GBM), 256, GSMEM>>>(hh, hl, wth + OWT, wtl + OWT,
                                                     ob, out, 0, 0, OUTD, DM, 0, 0);
}

// round 9
// speedup vs baseline: 1.5034x; 1.0084x over previous
#include <cuda_runtime.h>
#include <cuda_bf16.h>
#include <math.h>
#include <stdint.h>

#define NB 32
#define SS 512
#define DM 256
#define NH 8
#define HDIM 64
#define NLAYER 5
#define FFD 1024
#define OUTD 4096
#define NT (NB*SS)     /* 16384 tokens */
#define QKV 512        /* H*HD */

// ---------------- scratch (no allocations allowed) ----------------
__device__ float g_h [NT*DM];
__device__ float g_p [NT*DM];
__device__ float g_pe[SS*DM];
__device__ float g_bqkv[NLAYER*1536];
__device__ __nv_bfloat16 g_hh [NT*DM];
__device__ __nv_bfloat16 g_hl [NT*DM];
__device__ __nv_bfloat16 g_qkvh[NT*1536];
__device__ __nv_bfloat16 g_qkvl[NT*1536];
__device__ __nv_bfloat16 g_ohi[NT*QKV];
__device__ __nv_bfloat16 g_olo[NT*QKV];
__device__ __nv_bfloat16 g_ffh[NT*FFD];
__device__ __nv_bfloat16 g_ffl[NT*FFD];
#define WT_TOTAL 6291456
__device__ __nv_bfloat16 g_wth[WT_TOTAL];
__device__ __nv_bfloat16 g_wtl[WT_TOTAL];

// weight-transpose offsets (elements); wq/wk/wv contiguous per layer -> fused QKV B
#define WQT(i) ((size_t)(i)*1048576)
#define WOT(i) (WQT(i)+393216)
#define W1T(i) (WQT(i)+524288)
#define W2T(i) (WQT(i)+786432)
#define OWT    ((size_t)5242880)

// ---------------- helpers ----------------
__device__ __forceinline__ uint32_t smem_u32(const void* p) {
    uint32_t a;
    asm("{ .reg .u64 t; cvta.to.shared.u64 t, %1; cvt.u32.u64 %0, t; }" : "=r"(a) : "l"(p));
    return a;
}
__device__ __forceinline__ void split_bf16(float v, __nv_bfloat16& hi, __nv_bfloat16& lo) {
    hi = __float2bfloat16(v);
    lo = __float2bfloat16(v - __bfloat162float(hi));
}
__device__ __forceinline__ void split2(float a, float b, uint32_t& hi, uint32_t& lo) {
    __nv_bfloat16 ha = __float2bfloat16(a), hb = __float2bfloat16(b);
    __nv_bfloat16 la = __float2bfloat16(a - __bfloat162float(ha));
    __nv_bfloat16 lb = __float2bfloat16(b - __bfloat162float(hb));
    __nv_bfloat162 ph; ph.x = ha; ph.y = hb;
    __nv_bfloat162 pl; pl.x = la; pl.y = lb;
    hi = *(uint32_t*)&ph; lo = *(uint32_t*)&pl;
}
__device__ __forceinline__ void cp16(uint32_t dst, const void* src) {
    asm volatile("cp.async.cg.shared.global [%0], [%1], 16;" :: "r"(dst), "l"(src));
}
__device__ __forceinline__ void ldmx4(uint32_t* r, uint32_t addr) {
    asm volatile("ldmatrix.sync.aligned.m8n8.x4.shared.b16 {%0,%1,%2,%3}, [%4];"
        : "=r"(r[0]), "=r"(r[1]), "=r"(r[2]), "=r"(r[3]) : "r"(addr));
}
__device__ __forceinline__ void ldmx4t(uint32_t* r, uint32_t addr) {
    asm volatile("ldmatrix.sync.aligned.m8n8.x4.trans.shared.b16 {%0,%1,%2,%3}, [%4];"
        : "=r"(r[0]), "=r"(r[1]), "=r"(r[2]), "=r"(r[3]) : "r"(addr));
}
__device__ __forceinline__ void mma16816(float* d, const uint32_t* a, const uint32_t* b) {
    asm volatile("mma.sync.aligned.m16n8k16.row.col.f32.bf16.bf16.f32 "
        "{%0,%1,%2,%3}, {%4,%5,%6,%7}, {%8,%9}, {%0,%1,%2,%3};"
        : "+f"(d[0]), "+f"(d[1]), "+f"(d[2]), "+f"(d[3])
        : "r"(a[0]), "r"(a[1]), "r"(a[2]), "r"(a[3]), "r"(b[0]), "r"(b[1]));
}

// ---------------- positional encoding ----------------
__global__ void pe_kernel(float* __restrict__ pe) {
    int s = blockIdx.x, d = threadIdx.x;
    int i = d >> 1;
    float div = powf(10000.0f, (float)(2*i) / (float)DM);
    float ang = (float)s / div;
    pe[s*DM + d] = (d & 1) ? cosf(ang) : sinf(ang);
}

// ---------------- embedding + PE (+ bf16 split) ----------------
__global__ void embed_kernel(const int* __restrict__ x, const float* __restrict__ emb,
                             const float* __restrict__ pe, float* __restrict__ h,
                             __nv_bfloat16* __restrict__ hh, __nv_bfloat16* __restrict__ hl) {
    int t = blockIdx.x, d = threadIdx.x;
    int tok = x[t];
    int s = t & (SS-1);
    float v = emb[tok*DM + d] + pe[s*DM + d];
    h[(size_t)t*DM + d] = v;
    __nv_bfloat16 hi, lo; split_bf16(v, hi, lo);
    hh[(size_t)t*DM + d] = hi;
    hl[(size_t)t*DM + d] = lo;
}

// ---------------- pack QKV biases: [NL][1536] ----------------
__global__ void pack_bias(const float* __restrict__ bq, const float* __restrict__ bk,
                          const float* __restrict__ bv, float* __restrict__ out) {
    int i = blockIdx.x, d = threadIdx.x;
    out[i*1536 + d]        = bq[i*QKV + d];
    out[i*1536 + 512 + d]  = bk[i*QKV + d];
    out[i*1536 + 1024 + d] = bv[i*QKV + d];
}

// ---------------- weight transpose + split (layer-batched) ----------------
__global__ void wsplit(const float* __restrict__ W, __nv_bfloat16* __restrict__ Thi,
                       __nv_bfloat16* __restrict__ Tlo, int K, int N,
                       size_t lsrc, size_t ldst) {
    __shared__ float t[32][33];
    const float* Ws = W + (size_t)blockIdx.z * lsrc;
    __nv_bfloat16* Th = Thi + (size_t)blockIdx.z * ldst;
    __nv_bfloat16* Tl = Tlo + (size_t)blockIdx.z * ldst;
    int k0 = blockIdx.x*32, n0 = blockIdx.y*32;
    int tx = threadIdx.x, ty = threadIdx.y;  // 32 x 8
    #pragma unroll
    for (int i = 0; i < 32; i += 8)
        t[ty+i][tx] = Ws[(size_t)(k0+ty+i)*N + n0+tx];
    __syncthreads();
    #pragma unroll
    for (int i = 0; i < 32; i += 8) {
        float v = t[tx][ty+i];
        __nv_bfloat16 hi, lo; split_bf16(v, hi, lo);
        Th[(size_t)(n0+ty+i)*K + k0+tx] = hi;
        Tl[(size_t)(n0+ty+i)*K + k0+tx] = lo;
    }
}

// ---------------- HMMA bf16x3 GEMM (3-stage pipeline) ----------------
#define GBM 128
#define GBN 128
#define GBK 32
#define ROWB 80
#define TILEB (128*ROWB)
#define OFF_AHI 0
#define OFF_ALO TILEB
#define OFF_BHI (2*TILEB)
#define OFF_BLO (3*TILEB)
#define STAGEB (4*TILEB)
#define NSTAGE 3
#define GSMEM (NSTAGE*STAGEB)

__global__ void __launch_bounds__(256, 1)
gemm_mma(const __nv_bfloat16* __restrict__ Ahi, const __nv_bfloat16* __restrict__ Alo,
         const __nv_bfloat16* __restrict__ Bhi, const __nv_bfloat16* __restrict__ Blo,
         const float* __restrict__ bias,
         float* __restrict__ Cf, __nv_bfloat16* __restrict__ Chi, __nv_bfloat16* __restrict__ Clo,
         int Ncols, int K, int mode, int relu) {
    extern __shared__ char smem[];
    uint32_t sb = smem_u32(smem);
    int tid = threadIdx.x;
    int lane = tid & 31;
    int wid = tid >> 5;
    int warp_m = wid & 1;
    int warp_n = wid >> 1;
    int row0 = blockIdx.y * GBM;
    int col0 = blockIdx.x * GBN;

    int lr  = tid >> 2;
    int lc  = tid & 3;
    uint32_t sm_off0 = (uint32_t)(lr * ROWB + lc * 16);
    uint32_t sm_off1 = (uint32_t)((lr + 64) * ROWB + lc * 16);

#define LOAD_STAGE(bufidx, chunk) do { \
    uint32_t so = sb + (uint32_t)(bufidx)*STAGEB; \
    int kc = (chunk)*GBK + lc*8; \
    size_t ga0 = (size_t)(row0 + lr)      * K + kc; \
    size_t ga1 = (size_t)(row0 + lr + 64) * K + kc; \
    size_t gb0 = (size_t)(col0 + lr)      * K + kc; \
    size_t gb1 = (size_t)(col0 + lr + 64) * K + kc; \
    cp16(so + OFF_AHI + sm_off0, Ahi + ga0); \
    cp16(so + OFF_AHI + sm_off1, Ahi + ga1); \
    cp16(so + OFF_ALO + sm_off0, Alo + ga0); \
    cp16(so + OFF_ALO + sm_off1, Alo + ga1); \
    cp16(so + OFF_BHI + sm_off0, Bhi + gb0); \
    cp16(so + OFF_BHI + sm_off1, Bhi + gb1); \
    cp16(so + OFF_BLO + sm_off0, Blo + gb0); \
    cp16(so + OFF_BLO + sm_off1, Blo + gb1); \
} while(0)

    uint32_t a_row = (uint32_t)(warp_m*64 + (lane & 15));
    uint32_t a_off = a_row * ROWB + ((uint32_t)(lane >> 4)) * 16;
    uint32_t b_row = (uint32_t)(warp_n*32 + (lane & 7) + ((lane >> 4) << 3));
    uint32_t b_off = b_row * ROWB + ((uint32_t)((lane >> 3) & 1)) * 16;

    float acc[4][4][4];
    #pragma unroll
    for (int i = 0; i < 4; i++)
        #pragma unroll
        for (int j = 0; j < 4; j++)
            #pragma unroll
            for (int e = 0; e < 4; e++) acc[i][j][e] = 0.0f;

    int nch = K / GBK;
    LOAD_STAGE(0, 0);
    asm volatile("cp.async.commit_group;" ::: "memory");
    LOAD_STAGE(1, 1);
    asm volatile("cp.async.commit_group;" ::: "memory");

    int buf = 0;
    for (int c = 0; c < nch; c++) {
        if (c + 1 < nch) {
            asm volatile("cp.async.wait_group 1;" ::: "memory");
        } else {
            asm volatile("cp.async.wait_group 0;" ::: "memory");
        }
        __syncthreads();
        if (c + 2 < nch) {
            int nb = buf + 2; if (nb >= NSTAGE) nb -= NSTAGE;
            LOAD_STAGE(nb, c + 2);
            asm volatile("cp.async.commit_group;" ::: "memory");
        }

        uint32_t so = sb + (uint32_t)buf * STAGEB;

        // load ALL fragments for both k-steps up front (long LDSM window)
        uint32_t ah[2][4][4], al[2][4][4], bh[2][2][4], bl[2][2][4];
        #pragma unroll
        for (int s = 0; s < 2; s++) {
            uint32_t ks = (uint32_t)(s * 32);
            #pragma unroll
            for (int mi = 0; mi < 4; mi++) {
                uint32_t ao = a_off + (uint32_t)(mi*16) * ROWB + ks;
                ldmx4(ah[s][mi], so + OFF_AHI + ao);
                ldmx4(al[s][mi], so + OFF_ALO + ao);
            }
            #pragma unroll
            for (int nt = 0; nt < 2; nt++) {
                uint32_t bo = b_off + (uint32_t)(nt*16) * ROWB + ks;
                ldmx4(bh[s][nt], so + OFF_BHI + bo);
                ldmx4(bl[s][nt], so + OFF_BLO + bo);
            }
        }
        #pragma unroll
        for (int s = 0; s < 2; s++) {
            #pragma unroll
            for (int mi = 0; mi < 4; mi++)
                #pragma unroll
                for (int nj = 0; nj < 4; nj++) {
                    const uint32_t* ph = &bh[s][nj >> 1][(nj & 1) * 2];
                    const uint32_t* pl = &bl[s][nj >> 1][(nj & 1) * 2];
                    mma16816(acc[mi][nj], ah[s][mi], ph);
                    mma16816(acc[mi][nj], ah[s][mi], pl);
                    mma16816(acc[mi][nj], al[s][mi], ph);
                }
        }
        __syncthreads();
        buf++; if (buf >= NSTAGE) buf = 0;
    }

    int em = row0 + warp_m*64 + (lane >> 2);
    int en = col0 + warp_n*32 + (lane & 3) * 2;
    #pragma unroll
    for (int mi = 0; mi < 4; mi++) {
        #pragma unroll
        for (int nj = 0; nj < 4; nj++) {
            int cc = en + nj*8;
            float b0 = bias[cc], b1 = bias[cc + 1];
            #pragma unroll
            for (int half = 0; half < 2; half++) {
                int rr = em + mi*16 + half*8;
                float v0 = acc[mi][nj][half*2 + 0] + b0;
                float v1 = acc[mi][nj][half*2 + 1] + b1;
                if (relu) { v0 = fmaxf(v0, 0.0f); v1 = fmaxf(v1, 0.0f); }
                size_t idx = (size_t)rr * Ncols + cc;
                if (mode == 0) {
                    *(float2*)(Cf + idx) = make_float2(v0, v1);
                } else {
                    uint32_t hi, lo;
                    split2(v0, v1, hi, lo);
                    *(uint32_t*)(Chi + idx) = hi;
                    *(uint32_t*)(Clo + idx) = lo;
                }
            }
        }
    }
#undef LOAD_STAGE
}

// ---------------- HMMA flash attention (bf16x3, 128 queries/CTA, double-buffered K/V) ----------------
// grid (SS/128, B*H), 256 threads (8 warps x m16). QKV packed [t][1536] hi/lo.
#define ATS 144                 /* bytes per 64-bf16 row (128 data + 16 pad) */
#define ATILE (64*ATS)          /* 9216 */
#define ASTAGE (4*ATILE)        /* Khi,Klo,Vhi,Vlo = 36864 */
#define ASMEM (2*ASTAGE)        /* 73728 */

__global__ void __launch_bounds__(256, 2)
attn_mma(const __nv_bfloat16* __restrict__ Xh, const __nv_bfloat16* __restrict__ Xl,
         __nv_bfloat16* __restrict__ Ohi, __nv_bfloat16* __restrict__ Olo) {
    extern __shared__ char smem[];
    uint32_t sb = smem_u32(smem);

    int tid = threadIdx.x, lane = tid & 31, w = tid >> 5;
    int qt = blockIdx.x, bh = blockIdx.y;
    int b = bh >> 3, h = bh & 7;
    int q0 = qt * 128;
    size_t gq = ((size_t)b * SS) * 1536 + h * HDIM;

    // ---- load Q (128 rows, hi/lo) into stage-0 region temporarily ----
    {
        int r = tid >> 1, cg = (tid & 1) * 4;
        size_t go = gq + (size_t)(q0 + r) * 1536 + cg * 8;
        uint32_t so = (uint32_t)(r * ATS + cg * 16);
        #pragma unroll
        for (int c = 0; c < 4; c++) {
            cp16(sb + so + c*16, Xh + go + c*8);
            cp16(sb + 2*ATILE + so + c*16, Xl + go + c*8);
        }
    }
    asm volatile("cp.async.commit_group;" ::: "memory");
    asm volatile("cp.async.wait_group 0;" ::: "memory");
    __syncthreads();

    uint32_t qh[4][4], ql[4][4];
    #pragma unroll
    for (int ks = 0; ks < 4; ks++) {
        uint32_t ao = (uint32_t)((w*16 + (lane & 15)) * ATS + (lane >> 4)*16 + ks*32);
        ldmx4(qh[ks], sb + ao);
        ldmx4(ql[ks], sb + 2*ATILE + ao);
    }
    __syncthreads();   // all warps done reading Q before stage-0 K/V overwrites

    // ---- K/V stage loader ----
#define LOADKV(stage, kt) do { \
    int quad = tid >> 6, r = tid & 63; \
    const __nv_bfloat16* src = (quad == 0 || quad == 2) ? Xh : Xl; \
    int coladd = (quad < 2) ? 512 : 1024; \
    size_t go = gq + (size_t)((kt)*64 + r) * 1536 + coladd; \
    uint32_t dst = sb + (uint32_t)(stage)*ASTAGE + (uint32_t)quad*ATILE + (uint32_t)(r * ATS); \
    _Pragma("unroll") \
    for (int c = 0; c < 8; c++) cp16(dst + c*16, src + go + c*8); \
} while(0)

    float mrow0 = -1e30f, mrow1 = -1e30f, lrow0 = 0.0f, lrow1 = 0.0f;
    float o[8][4];
    #pragma unroll
    for (int dt = 0; dt < 8; dt++)
        #pragma unroll
        for (int e = 0; e < 4; e++) o[dt][e] = 0.0f;

    int ktmax = 2*qt + 1;
    LOADKV(0, 0);
    asm volatile("cp.async.commit_group;" ::: "memory");

    int qrA = q0 + w*16 + (lane >> 2);

    for (int kt = 0; kt <= ktmax; kt++) {
        if (kt < ktmax) {
            LOADKV((kt + 1) & 1, kt + 1);
            asm volatile("cp.async.commit_group;" ::: "memory");
            asm volatile("cp.async.wait_group 1;" ::: "memory");
        } else {
            asm volatile("cp.async.wait_group 0;" ::: "memory");
        }
        __syncthreads();

        uint32_t so = sb + (uint32_t)(kt & 1) * ASTAGE;
        uint32_t sKh = so, sKl = so + ATILE, sVh = so + 2*ATILE, sVl = so + 3*ATILE;

        // scores S = Q K^T (bf16x3)
        float s[8][4];
        #pragma unroll
        for (int nt = 0; nt < 8; nt++)
            #pragma unroll
            for (int e = 0; e < 4; e++) s[nt][e] = 0.0f;

        #pragma unroll
        for (int p = 0; p < 4; p++) {
            #pragma unroll
            for (int ks = 0; ks < 4; ks++) {
                uint32_t kfh[4], kfl[4];
                uint32_t bo = (uint32_t)((p*16 + (lane & 7) + ((lane >> 4) << 3)) * ATS
                                         + ((lane >> 3) & 1)*16 + ks*32);
                ldmx4(kfh, sKh + bo);
                ldmx4(kfl, sKl + bo);
                mma16816(s[2*p],   qh[ks], &kfh[0]);
                mma16816(s[2*p],   qh[ks], &kfl[0]);
                mma16816(s[2*p],   ql[ks], &kfh[0]);
                mma16816(s[2*p+1], qh[ks], &kfh[2]);
                mma16816(s[2*p+1], qh[ks], &kfl[2]);
                mma16816(s[2*p+1], ql[ks], &kfh[2]);
            }
        }

        // scale + causal mask (always applied; kt can exceed this warp's diagonal)
        #pragma unroll
        for (int nt = 0; nt < 8; nt++)
            #pragma unroll
            for (int e = 0; e < 4; e++) {
                float sv = s[nt][e] * 0.125f;
                int col = kt*64 + nt*8 + 2*(lane & 3) + (e & 1);
                int qr = qrA + ((e >> 1) << 3);
                if (col > qr) sv = -1e30f;
                s[nt][e] = sv;
            }

        // online softmax (rows A: regs 0,1; rows B: regs 2,3)
        float mx0 = -1e30f, mx1 = -1e30f;
        #pragma unroll
        for (int nt = 0; nt < 8; nt++) {
            mx0 = fmaxf(mx0, fmaxf(s[nt][0], s[nt][1]));
            mx1 = fmaxf(mx1, fmaxf(s[nt][2], s[nt][3]));
        }
        mx0 = fmaxf(mx0, __shfl_xor_sync(0xffffffffu, mx0, 1));
        mx0 = fmaxf(mx0, __shfl_xor_sync(0xffffffffu, mx0, 2));
        mx1 = fmaxf(mx1, __shfl_xor_sync(0xffffffffu, mx1, 1));
        mx1 = fmaxf(mx1, __shfl_xor_sync(0xffffffffu, mx1, 2));
        float mn0 = fmaxf(mrow0, mx0), mn1 = fmaxf(mrow1, mx1);
        float c0 = __expf(mrow0 - mn0), c1 = __expf(mrow1 - mn1);
        mrow0 = mn0; mrow1 = mn1;
        float rs0 = 0.0f, rs1 = 0.0f;
        #pragma unroll
        for (int nt = 0; nt < 8; nt++) {
            s[nt][0] = __expf(s[nt][0] - mn0); rs0 += s[nt][0];
            s[nt][1] = __expf(s[nt][1] - mn0); rs0 += s[nt][1];
            s[nt][2] = __expf(s[nt][2] - mn1); rs1 += s[nt][2];
            s[nt][3] = __expf(s[nt][3] - mn1); rs1 += s[nt][3];
        }
        rs0 += __shfl_xor_sync(0xffffffffu, rs0, 1);
        rs0 += __shfl_xor_sync(0xffffffffu, rs0, 2);
        rs1 += __shfl_xor_sync(0xffffffffu, rs1, 1);
        rs1 += __shfl_xor_sync(0xffffffffu, rs1, 2);
        lrow0 = lrow0 * c0 + rs0;
        lrow1 = lrow1 * c1 + rs1;
        #pragma unroll
        for (int dt = 0; dt < 8; dt++) {
            o[dt][0] *= c0; o[dt][1] *= c0;
            o[dt][2] *= c1; o[dt][3] *= c1;
        }

        // O += P V (bf16x3), P fragments built register-locally from score C-frags
        #pragma unroll
        for (int kc = 0; kc < 4; kc++) {
            uint32_t aph[4], apl[4];
            split2(s[2*kc][0],   s[2*kc][1],   aph[0], apl[0]);
            split2(s[2*kc][2],   s[2*kc][3],   aph[1], apl[1]);
            split2(s[2*kc+1][0], s[2*kc+1][1], aph[2], apl[2]);
            split2(s[2*kc+1][2], s[2*kc+1][3], aph[3], apl[3]);
            #pragma unroll
            for (int dt = 0; dt < 4; dt++) {
                uint32_t vfh[4], vfl[4];
                uint32_t vo = (uint32_t)((kc*16 + (lane & 15)) * ATS + dt*32 + (lane >> 4)*16);
                ldmx4t(vfh, sVh + vo);
                ldmx4t(vfl, sVl + vo);
                mma16816(o[2*dt],   aph, &vfh[0]);
                mma16816(o[2*dt],   aph, &vfl[0]);
                mma16816(o[2*dt],   apl, &vfh[0]);
                mma16816(o[2*dt+1], aph, &vfh[2]);
                mma16816(o[2*dt+1], aph, &vfl[2]);
                mma16816(o[2*dt+1], apl, &vfh[2]);
            }
        }
        __syncthreads();   // compute done before next stage load overwrites
    }

    // epilogue: normalize + split-bf16 store
    float i0 = 1.0f / lrow0, i1 = 1.0f / lrow1;
    int qA = q0 + w*16 + (lane >> 2);
    size_t ob = ((size_t)b * SS) * QKV + h * HDIM;
    #pragma unroll
    for (int dt = 0; dt < 8; dt++) {
        int d = dt*8 + 2*(lane & 3);
        uint32_t hi, lo;
        float v0 = o[dt][0] * i0, v1 = o[dt][1] * i0;
        split2(v0, v1, hi, lo);
        size_t idxA = ob + (size_t)qA * QKV + d;
        *(uint32_t*)(Ohi + idxA) = hi;
        *(uint32_t*)(Olo + idxA) = lo;
        v0 = o[dt][2] * i1; v1 = o[dt][3] * i1;
        split2(v0, v1, hi, lo);
        size_t idxB = ob + (size_t)(qA + 8) * QKV + d;
        *(uint32_t*)(Ohi + idxB) = hi;
        *(uint32_t*)(Olo + idxB) = lo;
    }
#undef LOADKV
}

// ---------------- fused residual add + LayerNorm (+ bf16 split) ----------------
__global__ void add_ln_kernel(float* __restrict__ h, const float* __restrict__ r,
                              const float* __restrict__ s, const float* __restrict__ b,
                              __nv_bfloat16* __restrict__ hh, __nv_bfloat16* __restrict__ hl) {
    __shared__ float red[12];
    int t = blockIdx.x;
    int d = threadIdx.x;
    int lane = d & 31, w = d >> 5;

    float v = h[(size_t)t*DM + d] + r[(size_t)t*DM + d];

    float sum = v;
    #pragma unroll
    for (int off = 16; off >= 1; off >>= 1) sum += __shfl_xor_sync(0xffffffffu, sum, off);
    if (lane == 0) red[w] = sum;
    __syncthreads();
    if (d == 0) { float tt = 0; for (int i = 0; i < 8; i++) tt += red[i]; red[8] = tt; }
    __syncthreads();
    float mean = red[8] * (1.0f/DM);

    float dv = v - mean;
    float sq = dv*dv;
    #pragma unroll
    for (int off = 16; off >= 1; off >>= 1) sq += __shfl_xor_sync(0xffffffffu, sq, off);
    if (lane == 0) red[w] = sq;
    __syncthreads();
    if (d == 0) { float tt = 0; for (int i = 0; i < 8; i++) tt += red[i]; red[9] = tt; }
    __syncthreads();
    float var = red[9] * (1.0f/DM);

    float out = dv * rsqrtf(var + 1e-5f) * s[d] + b[d];
    h[(size_t)t*DM + d] = out;
    __nv_bfloat16 hi, lo; split_bf16(out, hi, lo);
    hh[(size_t)t*DM + d] = hi;
    hl[(size_t)t*DM + d] = lo;
}

// ---------------- launch ----------------
extern "C" void kernel_launch(void* const* d_in, const int* in_sizes, int n_in,
                              void* d_out, int out_size) {
    (void)in_sizes; (void)n_in; (void)out_size;
    const int*   x    = (const int*)  d_in[0];
    const float* emb  = (const float*)d_in[1];
    const float* wq   = (const float*)d_in[2];
    const float* bq   = (const float*)d_in[3];
    const float* wk   = (const float*)d_in[4];
    const float* bk   = (const float*)d_in[5];
    const float* wv   = (const float*)d_in[6];
    const float* bv   = (const float*)d_in[7];
    const float* wo   = (const float*)d_in[8];
    const float* bo   = (const float*)d_in[9];
    const float* ln1s = (const float*)d_in[10];
    const float* ln1b = (const float*)d_in[11];
    const float* w1   = (const float*)d_in[12];
    const float* b1   = (const float*)d_in[13];
    const float* w2   = (const float*)d_in[14];
    const float* b2   = (const float*)d_in[15];
    const float* ln2s = (const float*)d_in[16];
    const float* ln2b = (const float*)d_in[17];
    const float* ow   = (const float*)d_in[18];
    const float* ob   = (const float*)d_in[19];
    float* out = (float*)d_out;

    float *h, *p, *pe, *bqkv;
    __nv_bfloat16 *hh, *hl, *qkvh, *qkvl, *ohi, *olo, *ffh, *ffl, *wth, *wtl;
    cudaGetSymbolAddress((void**)&h,    g_h);
    cudaGetSymbolAddress((void**)&p,    g_p);
    cudaGetSymbolAddress((void**)&pe,   g_pe);
    cudaGetSymbolAddress((void**)&bqkv, g_bqkv);
    cudaGetSymbolAddress((void**)&hh,   g_hh);
    cudaGetSymbolAddress((void**)&hl,   g_hl);
    cudaGetSymbolAddress((void**)&qkvh, g_qkvh);
    cudaGetSymbolAddress((void**)&qkvl, g_qkvl);
    cudaGetSymbolAddress((void**)&ohi,  g_ohi);
    cudaGetSymbolAddress((void**)&olo,  g_olo);
    cudaGetSymbolAddress((void**)&ffh,  g_ffh);
    cudaGetSymbolAddress((void**)&ffl,  g_ffl);
    cudaGetSymbolAddress((void**)&wth,  g_wth);
    cudaGetSymbolAddress((void**)&wtl,  g_wtl);

    static int attr_set = 0;
    if (!attr_set) {
        cudaFuncSetAttribute(gemm_mma, cudaFuncAttributeMaxDynamicSharedMemorySize, GSMEM);
        cudaFuncSetAttribute(attn_mma, cudaFuncAttributeMaxDynamicSharedMemorySize, ASMEM);
        attr_set = 1;
    }

    dim3 wblk(32, 8);
    wsplit<<<dim3(DM/32,  QKV/32,  NLAYER), wblk>>>(wq, wth + 0,      wtl + 0,      DM,  QKV,  (size_t)DM*QKV,  1048576);
    wsplit<<<dim3(DM/32,  QKV/32,  NLAYER), wblk>>>(wk, wth + 131072, wtl + 131072, DM,  QKV,  (size_t)DM*QKV,  1048576);
    wsplit<<<dim3(DM/32,  QKV/32,  NLAYER), wblk>>>(wv, wth + 262144, wtl + 262144, DM,  QKV,  (size_t)DM*QKV,  1048576);
    wsplit<<<dim3(QKV/32, DM/32,   NLAYER), wblk>>>(wo, wth + 393216, wtl + 393216, QKV, DM,   (size_t)QKV*DM,  1048576);
    wsplit<<<dim3(DM/32,  FFD/32,  NLAYER), wblk>>>(w1, wth + 524288, wtl + 524288, DM,  FFD,  (size_t)DM*FFD,  1048576);
    wsplit<<<dim3(FFD/32, DM/32,   NLAYER), wblk>>>(w2, wth + 786432, wtl + 786432, FFD, DM,   (size_t)FFD*DM,  1048576);
    wsplit<<<dim3(DM/32,  OUTD/32, 1),      wblk>>>(ow, wth + OWT,    wtl + OWT,    DM,  OUTD, 0, 0);
    pack_bias<<<NLAYER, 512>>>(bq, bk, bv, bqkv);

    pe_kernel   <<<SS, DM>>>(pe);
    embed_kernel<<<NT, DM>>>(x, emb, pe, h, hh, hl);

    for (int i = 0; i < NLAYER; i++) {
        gemm_mma<<<dim3(1536/GBN, NT/GBM), 256, GSMEM>>>(hh, hl, wth + WQT(i), wtl + WQT(i),
                                                         bqkv + i*1536, 0, qkvh, qkvl, 1536, DM, 1, 0);
        attn_mma<<<dim3(SS/128, NB*NH), 256, ASMEM>>>(qkvh, qkvl, ohi, olo);
        gemm_mma<<<dim3(DM/GBN, NT/GBM), 256, GSMEM>>>(ohi, olo, wth + WOT(i), wtl + WOT(i),
                                                       bo + i*DM, p, 0, 0, DM, QKV, 0, 0);
        add_ln_kernel<<<NT, DM>>>(h, p, ln1s + i*DM, ln1b + i*DM, hh, hl);
        gemm_mma<<<dim3(FFD/GBN, NT/GBM), 256, GSMEM>>>(hh, hl, wth + W1T(i), wtl + W1T(i),
                                                        b1 + i*FFD, 0, ffh, ffl, FFD, DM, 1, 1);
        gemm_mma<<<dim3(DM/GBN, NT/GBM), 256, GSMEM>>>(ffh, ffl, wth + W2T(i), wtl + W2T(i),
                                                       b2 + i*DM, p, 0, 0, DM, FFD, 0, 0);
        add_ln_kernel<<<NT, DM>>>(h, p, ln2s + i*DM, ln2b + i*DM, hh, hl);
    }

    gemm_mma<<<dim3(OUTD/GBN, NT/GBM), 256, GSMEM>>>(hh, hl, wth + OWT, wtl + OWT,
                                                     ob, out, 0, 0, OUTD, DM, 0, 0);
}